// round 8
// baseline (speedup 1.0000x reference)
#include <cuda_runtime.h>

#define SELU_SCALE 1.0507009873554804934193349852946f
#define SELU_ALPHA 1.6732632423543772848170429916717f

// R5 body (4 pts/thread, float4/int4 coalesced, streaming hints) wrapped in a
// grid-stride persistent loop: 148 SMs x 6 CTAs resident, no wave transitions,
// and iteration-level overlap of next loads with previous stores.
__global__ __launch_bounds__(256, 6) void ifs_kernel(
    const float4* __restrict__ pts,      // points as float4: 3 float4 per 4 points
    const float4* __restrict__ pcol,     // prev_colors likewise
    const int4*   __restrict__ chs,      // choices: 1 int4 per 4 points
    const float*  __restrict__ matrices, // [K,3,3] = 72 floats
    const float*  __restrict__ biases,   // [K,3]   = 24 floats
    const float*  __restrict__ colors,   // [K,3]   = 24 floats
    float4* __restrict__ out_tp,         // tp output, 3 float4 per 4 points
    float4* __restrict__ out_col,        // new_colors output
    int nquads)                          // N/4
{
    __shared__ float sM[72];
    __shared__ float sB[24];
    __shared__ float sC[24];
    {
        int t = threadIdx.x;
        if (t < 72) sM[t] = matrices[t];
        if (t < 24) sB[t] = biases[t];
        else if (t >= 32 && t < 56) sC[t - 32] = colors[t - 32];
    }
    __syncthreads();

    int stride = gridDim.x * blockDim.x;
    for (int i = blockIdx.x * blockDim.x + threadIdx.x; i < nquads; i += stride) {
        float4 p0 = __ldcs(&pts[3 * i + 0]);
        float4 p1 = __ldcs(&pts[3 * i + 1]);
        float4 p2 = __ldcs(&pts[3 * i + 2]);
        float4 c0 = __ldcs(&pcol[3 * i + 0]);
        float4 c1 = __ldcs(&pcol[3 * i + 1]);
        float4 c2 = __ldcs(&pcol[3 * i + 2]);
        int4   ch = __ldcs(&chs[i]);

        float px[4][3] = {
            {p0.x, p0.y, p0.z},
            {p0.w, p1.x, p1.y},
            {p1.z, p1.w, p2.x},
            {p2.y, p2.z, p2.w}
        };
        float pc[4][3] = {
            {c0.x, c0.y, c0.z},
            {c0.w, c1.x, c1.y},
            {c1.z, c1.w, c2.x},
            {c2.y, c2.z, c2.w}
        };
        int cc[4] = {ch.x, ch.y, ch.z, ch.w};

        float tp[4][3];
        float nc[4][3];

#pragma unroll
        for (int j = 0; j < 4; j++) {
            int c = cc[j];
            const float* M = sM + c * 9;
            const float* B = sB + c * 3;
            const float* C = sC + c * 3;
            float x = px[j][0], y = px[j][1], z = px[j][2];
#pragma unroll
            for (int e = 0; e < 3; e++) {
                // tp[e] = sum_d p[d] * M[d][e] + b[e] (contract over FIRST axis)
                float v = fmaf(x, M[0 * 3 + e], fmaf(y, M[1 * 3 + e], fmaf(z, M[2 * 3 + e], B[e])));
                float neg = SELU_SCALE * SELU_ALPHA * (__expf(v) - 1.0f);
                float pos = SELU_SCALE * v;
                tp[j][e] = v > 0.0f ? pos : neg;
                nc[j][e] = (pc[j][e] + C[e]) * 0.5f;
            }
        }

        __stcs(&out_tp[3 * i + 0], make_float4(tp[0][0], tp[0][1], tp[0][2], tp[1][0]));
        __stcs(&out_tp[3 * i + 1], make_float4(tp[1][1], tp[1][2], tp[2][0], tp[2][1]));
        __stcs(&out_tp[3 * i + 2], make_float4(tp[2][2], tp[3][0], tp[3][1], tp[3][2]));

        __stcs(&out_col[3 * i + 0], make_float4(nc[0][0], nc[0][1], nc[0][2], nc[1][0]));
        __stcs(&out_col[3 * i + 1], make_float4(nc[1][1], nc[1][2], nc[2][0], nc[2][1]));
        __stcs(&out_col[3 * i + 2], make_float4(nc[2][2], nc[3][0], nc[3][1], nc[3][2]));
    }
}

extern "C" void kernel_launch(void* const* d_in, const int* in_sizes, int n_in,
                              void* d_out, int out_size)
{
    const float4* pts      = (const float4*)d_in[0];  // points      [N,3] f32
    const float4* pcol     = (const float4*)d_in[1];  // prev_colors [N,3] f32
    const int4*   chs      = (const int4*)d_in[2];    // choices     [N]   i32
    const float*  matrices = (const float*)d_in[3];   // [K,3,3]
    const float*  biases   = (const float*)d_in[4];   // [K,3]
    const float*  colors   = (const float*)d_in[5];   // [K,3]

    int N = in_sizes[2];          // choices element count == N
    int nquads = N / 4;

    // Persistent grid: 148 SMs x 6 CTAs/SM resident (regs capped via launch_bounds)
    int blocks = 148 * 6;
    ifs_kernel<<<blocks, 256>>>(pts, pcol, chs, matrices, biases, colors,
                                (float4*)d_out,
                                (float4*)((float*)d_out + (size_t)N * 3),
                                nquads);
}

// round 10
// speedup vs baseline: 1.4613x; 1.4613x over previous
#include <cuda_runtime.h>

#define SELU_SCALE 1.0507009873554804934193349852946f
#define SELU_ALPHA 1.6732632423543772848170429916717f

// Converged configuration (R5): 4 points/thread, all traffic float4/int4
// coalesced with streaming (evict-first) hints, natural register allocation
// (38 regs, 6 CTAs/SM). Probes showed every deviation regresses:
//   - 8 pts/thread (MLP 14, occ 33%): 148.6us — warp count feeds DRAM, not MLP
//   - forced 32 regs / occ 87%:       144.9us — interleaved schedule hurt
//   - persistent grid-stride:         201us   — loop serializes iterations
// choices int4 issued first: it gates the smem gathers, so it gets the most
// latency cover from the six float4 loads behind it.
__global__ __launch_bounds__(256) void ifs_kernel(
    const float4* __restrict__ pts,      // points as float4: 3 float4 per 4 points
    const float4* __restrict__ pcol,     // prev_colors likewise
    const int4*   __restrict__ chs,      // choices: 1 int4 per 4 points
    const float*  __restrict__ matrices, // [K,3,3] = 72 floats
    const float*  __restrict__ biases,   // [K,3]   = 24 floats
    const float*  __restrict__ colors,   // [K,3]   = 24 floats
    float4* __restrict__ out_tp,         // tp output, 3 float4 per 4 points
    float4* __restrict__ out_col,        // new_colors output
    int nquads)                          // N/4
{
    __shared__ float sM[72];
    __shared__ float sB[24];
    __shared__ float sC[24];
    {
        int t = threadIdx.x;
        if (t < 72) sM[t] = matrices[t];
        if (t < 24) sB[t] = biases[t];
        else if (t >= 32 && t < 56) sC[t - 32] = colors[t - 32];
    }
    __syncthreads();

    int i = blockIdx.x * blockDim.x + threadIdx.x;
    if (i >= nquads) return;

    int4   ch = __ldcs(&chs[i]);
    float4 p0 = __ldcs(&pts[3 * i + 0]);
    float4 p1 = __ldcs(&pts[3 * i + 1]);
    float4 p2 = __ldcs(&pts[3 * i + 2]);
    float4 c0 = __ldcs(&pcol[3 * i + 0]);
    float4 c1 = __ldcs(&pcol[3 * i + 1]);
    float4 c2 = __ldcs(&pcol[3 * i + 2]);

    float px[4][3] = {
        {p0.x, p0.y, p0.z},
        {p0.w, p1.x, p1.y},
        {p1.z, p1.w, p2.x},
        {p2.y, p2.z, p2.w}
    };
    float pc[4][3] = {
        {c0.x, c0.y, c0.z},
        {c0.w, c1.x, c1.y},
        {c1.z, c1.w, c2.x},
        {c2.y, c2.z, c2.w}
    };
    int cc[4] = {ch.x, ch.y, ch.z, ch.w};

    float tp[4][3];
    float nc[4][3];

#pragma unroll
    for (int j = 0; j < 4; j++) {
        int c = cc[j];
        const float* M = sM + c * 9;
        const float* B = sB + c * 3;
        const float* C = sC + c * 3;
        float x = px[j][0], y = px[j][1], z = px[j][2];
#pragma unroll
        for (int e = 0; e < 3; e++) {
            // tp[e] = sum_d p[d] * M[d][e] + b[e]  (contract over FIRST matrix axis)
            float v = fmaf(x, M[0 * 3 + e], fmaf(y, M[1 * 3 + e], fmaf(z, M[2 * 3 + e], B[e])));
            float neg = SELU_SCALE * SELU_ALPHA * (__expf(v) - 1.0f);
            float pos = SELU_SCALE * v;
            tp[j][e] = v > 0.0f ? pos : neg;
            nc[j][e] = (pc[j][e] + C[e]) * 0.5f;
        }
    }

    __stcs(&out_tp[3 * i + 0], make_float4(tp[0][0], tp[0][1], tp[0][2], tp[1][0]));
    __stcs(&out_tp[3 * i + 1], make_float4(tp[1][1], tp[1][2], tp[2][0], tp[2][1]));
    __stcs(&out_tp[3 * i + 2], make_float4(tp[2][2], tp[3][0], tp[3][1], tp[3][2]));

    __stcs(&out_col[3 * i + 0], make_float4(nc[0][0], nc[0][1], nc[0][2], nc[1][0]));
    __stcs(&out_col[3 * i + 1], make_float4(nc[1][1], nc[1][2], nc[2][0], nc[2][1]));
    __stcs(&out_col[3 * i + 2], make_float4(nc[2][2], nc[3][0], nc[3][1], nc[3][2]));
}

extern "C" void kernel_launch(void* const* d_in, const int* in_sizes, int n_in,
                              void* d_out, int out_size)
{
    const float4* pts      = (const float4*)d_in[0];  // points      [N,3] f32
    const float4* pcol     = (const float4*)d_in[1];  // prev_colors [N,3] f32
    const int4*   chs      = (const int4*)d_in[2];    // choices     [N]   i32
    const float*  matrices = (const float*)d_in[3];   // [K,3,3]
    const float*  biases   = (const float*)d_in[4];   // [K,3]
    const float*  colors   = (const float*)d_in[5];   // [K,3]

    int N = in_sizes[2];          // choices element count == N
    int nquads = N / 4;

    float* out = (float*)d_out;
    float4* out_tp  = (float4*)out;                    // first N*3 floats: tp
    float4* out_col = (float4*)(out + (size_t)N * 3);  // next N*3 floats: new_colors

    int threads = 256;
    int blocks = (nquads + threads - 1) / threads;
    ifs_kernel<<<blocks, threads>>>(pts, pcol, chs, matrices, biases, colors,
                                    out_tp, out_col, nquads);
}